// round 13
// baseline (speedup 1.0000x reference)
#include <cuda_runtime.h>
#include <cuda_bf16.h>
#include <stdint.h>
#include <math.h>

// ---------------------------------------------------------------------------
// B=16, C_IN=512, C_OUT=512, K=3, LAT=256, H=W=32.
// Modulated conv == plain conv (raw weights) + per-(b,oc) scale + bias.
// Implicit GEMM on mma.sync bf16 (3-pass hi/lo split: xh*wh+xh*wl+xl*wh).
// Round-13: 4-kernel launch sequence (border-zero merged into trans_x) so ncu
// captures conv_mma; B ldmatrix x4-fusion; early bl prefetch.
// ---------------------------------------------------------------------------
#define BATCH   16
#define CIN     512
#define COUT    512
#define LAT     256
#define KR      4608
#define XP      34
#define XPP     (XP * XP)
#define NXT     (BATCH * XPP * CIN)
#define NW      (COUT * CIN)

#define EQ_LIN_F 0.08838834764831845f

// ---- device scratch (allocation-free) ----
__device__ __nv_bfloat16 g_xth[NXT];     // [b][hp][wp][ic] hi
__device__ __nv_bfloat16 g_xtl[NXT];     // [b][hp][wp][ic] lo
__device__ __nv_bfloat16 g_wh[9 * NW];   // [tap][oc][ic]
__device__ __nv_bfloat16 g_wl[9 * NW];
__device__ float         g_scale[BATCH * COUT];

// ---------------------------------------------------------------------------
// helpers
// ---------------------------------------------------------------------------
__device__ __forceinline__ uint32_t smem_u32(const void* p) {
    uint32_t a;
    asm("{ .reg .u64 t; cvta.to.shared.u64 t, %1; cvt.u32.u64 %0, t; }"
        : "=r"(a) : "l"(p));
    return a;
}
#define SW128(o) ((o) ^ ((((unsigned)(o)) >> 3) & 0x70u))

#define LDM_X4(r0, r1, r2, r3, a) \
    asm volatile("ldmatrix.sync.aligned.m8n8.x4.shared.b16 {%0,%1,%2,%3}, [%4];" \
        : "=r"(r0), "=r"(r1), "=r"(r2), "=r"(r3) : "r"(a))

#define MMA16816(d, a, b) \
    asm volatile("mma.sync.aligned.m16n8k16.row.col.f32.bf16.bf16.f32 " \
        "{%0,%1,%2,%3}, {%4,%5,%6,%7}, {%8,%9}, {%0,%1,%2,%3};" \
        : "+f"((d)[0]), "+f"((d)[1]), "+f"((d)[2]), "+f"((d)[3]) \
        : "r"((a)[0]), "r"((a)[1]), "r"((a)[2]), "r"((a)[3]), \
          "r"((b)[0]), "r"((b)[1]))

#define CP16(dst, src) \
    asm volatile("cp.async.cg.shared.global [%0], [%1], 16;" :: "r"(dst), "l"(src))
#define CP_COMMIT()  asm volatile("cp.async.commit_group;")
#define CP_WAIT0()   asm volatile("cp.async.wait_group 0;" ::: "memory")
#define CP_WAIT1()   asm volatile("cp.async.wait_group 1;" ::: "memory")

// ---------------------------------------------------------------------------
// 1) transpose + split x -> xT[b][h+1][w+1][ic] hi/lo; by>=512 blocks write
//    the zero borders (hp or wp in {0,33}); disjoint from interior writes.
// ---------------------------------------------------------------------------
__global__ void trans_x_kernel(const float* __restrict__ x) {
    __shared__ float tile[32][33];
    const int tx = threadIdx.x, ty = threadIdx.y;
    const int tid = ty * 32 + tx;
    if (blockIdx.y >= 512) {
        // border path: 32 blocks x 256 threads, 132 elems each over
        // flatten = b(16) x pos(132) x ic(512) = 1,081,344
        const int base = ((int)blockIdx.y - 512) * 256 + tid;   // 0..8191
        for (int e = 0; e < 132; e++) {
            const int g = base + e * 8192;
            const int ic = g & 511;
            const int r  = g >> 9;          // b*132 + pos
            const int p  = r % 132;
            const int b  = r / 132;
            int hp, wp;
            if      (p < 34)  { hp = 0;       wp = p; }
            else if (p < 68)  { hp = 33;      wp = p - 34; }
            else if (p < 100) { hp = p - 67;  wp = 0; }
            else              { hp = p - 99;  wp = 33; }
            const size_t idx = ((size_t)(b * XP + hp) * XP + wp) * CIN + ic;
            g_xth[idx] = __float2bfloat16(0.f);
            g_xtl[idx] = __float2bfloat16(0.f);
        }
        return;
    }
    const int ic0 = blockIdx.x * 32;
    const int b   = blockIdx.y >> 5;
    const int h   = blockIdx.y & 31;
#pragma unroll
    for (int i = 0; i < 4; i++) {
        const int icl = ty + 8 * i;
        tile[icl][tx] = x[(((size_t)b * CIN + ic0 + icl) * 32 + h) * 32 + tx];
    }
    __syncthreads();
#pragma unroll
    for (int jj = 0; jj < 4; jj++) {
        const int j = ty + 8 * jj;
        const float v = tile[tx][j];
        const __nv_bfloat16 hi = __float2bfloat16(v);
        const size_t idx = ((size_t)(b * XP + h + 1) * XP + (j + 1)) * CIN + ic0 + tx;
        g_xth[idx] = hi;
        g_xtl[idx] = __float2bfloat16(v - __bfloat162float(hi));
    }
}

// ---------------------------------------------------------------------------
// 2) split + per-tap transpose weights -> g_wh/g_wl [tap][oc][ic]
// ---------------------------------------------------------------------------
__global__ void split_w_kernel(const float* __restrict__ w) {
    int i = blockIdx.x * blockDim.x + threadIdx.x;   // oc*512 + ic
    if (i >= NW) return;
    const float* src = w + (size_t)i * 9;
#pragma unroll
    for (int t = 0; t < 9; t++) {
        const float v = src[t];
        const __nv_bfloat16 h = __float2bfloat16(v);
        g_wh[(size_t)t * NW + i] = h;
        g_wl[(size_t)t * NW + i] = __float2bfloat16(v - __bfloat162float(h));
    }
}

// ---------------------------------------------------------------------------
// 3) per-(b,oc) effective scale; vectorized reduction
// ---------------------------------------------------------------------------
__global__ void scale_kernel(const float* __restrict__ W,
                             const float* __restrict__ style_w,
                             const float* __restrict__ lin_w,
                             const float* __restrict__ lin_b,
                             const float* __restrict__ mod_bias) {
    const int o = blockIdx.x;
    __shared__ float red[256];
    float ss = 0.f;
    const float4* wrow = (const float4*)(W + (size_t)o * KR);
    for (int i = threadIdx.x; i < KR / 4; i += 256) {
        const float4 v = wrow[i];
        ss += v.x * v.x + v.y * v.y + v.z * v.z + v.w * v.w;
    }
    red[threadIdx.x] = ss;
    __syncthreads();
#pragma unroll
    for (int s = 128; s > 0; s >>= 1) {
        if (threadIdx.x < s) red[threadIdx.x] += red[threadIdx.x + s];
        __syncthreads();
    }
    const float sumsq = red[0];
    if (threadIdx.x < BATCH) {
        const int b = threadIdx.x;
        const float4* st = (const float4*)(style_w + b * LAT);
        const float4* lw = (const float4*)(lin_w + (size_t)o * LAT);
        float dot = 0.f;
#pragma unroll 8
        for (int l = 0; l < LAT / 4; l++) {
            const float4 a = st[l], c = lw[l];
            dot += a.x * c.x + a.y * c.y + a.z * c.z + a.w * c.w;
        }
        const float eq_conv = sqrtf(2.0f / (float)KR);
        const float s = dot * EQ_LIN_F + lin_b[o] + 1.0f + mod_bias[o];
        g_scale[b * COUT + o] =
            eq_conv * s * rsqrtf(s * s * eq_conv * eq_conv * sumsq + 1e-8f);
    }
}

// ---------------------------------------------------------------------------
// 4) main mma.sync kernel, 3-stage pipeline.
//    CTA: M=128 x N=128; grid (4,128); 8 warps 2x4 -> 64x32 warp tiles.
//    144 iters (9 taps x 16 ic-chunks of 32). Stage 32KB: A[128m][32ic hi|lo],
//    B[128oc][same], SW128 rows. B frags loaded as ldmatrix.x4 pairs.
// ---------------------------------------------------------------------------
#define ITERS   144
#define STAGE   32768
#define SMEM_SZ (3 * STAGE + 1024)

__global__ __launch_bounds__(256, 2)
void conv_mma_kernel(const float* __restrict__ conv_bias, float* __restrict__ out) {
    extern __shared__ __align__(1024) char dsm[];
    const uint32_t sb = smem_u32(dsm);
    const uint32_t tb = (sb + 1023u) & ~1023u;

    const int t    = threadIdx.x;
    const int wid  = t >> 5, lane = t & 31;
    const int ocBase = blockIdx.x * 128;
    const int mT = blockIdx.y;
    const int b  = mT >> 3;
    const int h0 = (mT & 7) * 4;

    const int wm0 = (wid & 1) * 64;
    const int wn0 = (wid >> 1) * 32;

    // ---- hoisted fill addressing (per thread) ----
    const int q   = t & 7;
    const int v   = q >> 2;
    const int sub = q & 3;
    const int r5  = t >> 3;                       // 0..31
    const __nv_bfloat16* aPtr = v ? g_xtl : g_xth;
    const __nv_bfloat16* bPtr = v ? g_wl  : g_wh;
    uint32_t aDoff[4], bDoff[4];
    size_t   aBase[4], bBase[4];
#pragma unroll
    for (int kk = 0; kk < 4; kk++) {
        const int rowA = kk * 32 + r5;
        aDoff[kk] = SW128((uint32_t)(rowA << 7) + (v << 6) + (sub << 4));
        aBase[kk] = ((size_t)((b * XP + h0 + kk) * XP + r5) << 9) + (sub << 3);
        bDoff[kk] = aDoff[kk];
        bBase[kk] = ((size_t)(ocBase + rowA) << 9) + (sub << 3);
    }

    // fragment offsets (stage-relative) + row-XOR; addr = base+((off+kb)^xor)
    uint32_t aOff[4], aXor[4], bOff[2], bXor[2];
    {
        const int rA = lane & 15;
        const int ha = lane >> 4;
#pragma unroll
        for (int tm = 0; tm < 4; tm++) {
            const uint32_t off = (uint32_t)(wm0 + tm * 16 + rA) * 128u + ha * 16u;
            aOff[tm] = off;
            aXor[tm] = (off >> 3) & 0x70u;
        }
        // B x4: lanes 0-7 frag 2p rows k-lo, 8-15 frag 2p k-hi,
        //       16-23 frag 2p+1 k-lo, 24-31 frag 2p+1 k-hi
        const int rB = (lane & 7) + ((lane >> 4) & 1) * 8;   // row within 16
        const int hb = (lane >> 3) & 1;
#pragma unroll
        for (int p = 0; p < 2; p++) {
            const uint32_t off = (uint32_t)(wn0 + p * 16 + rB) * 128u + hb * 16u;
            bOff[p] = off;
            bXor[p] = (off >> 3) & 0x70u;
        }
    }

    float acc[4][4][4];
#pragma unroll
    for (int i = 0; i < 4; i++)
#pragma unroll
        for (int j = 0; j < 4; j++)
#pragma unroll
            for (int k = 0; k < 4; k++) acc[i][j][k] = 0.f;

    auto fill_stage = [&](int s, int it) {
        const int tap = it >> 4;
        const int ic0 = (it & 15) << 5;
        const int dh = tap / 3, dw = tap - dh * 3;
        const uint32_t uA = tb + s * STAGE;
        const uint32_t uB = uA + 16384;
        const size_t offA = ((size_t)(dh * XP + dw) << 9) + ic0;
        const size_t offB = (size_t)tap * NW + ic0;
#pragma unroll
        for (int kk = 0; kk < 4; kk++)
            CP16(uA + aDoff[kk], aPtr + aBase[kk] + offA);
#pragma unroll
        for (int kk = 0; kk < 4; kk++)
            CP16(uB + bDoff[kk], bPtr + bBase[kk] + offB);
        CP_COMMIT();
    };

    fill_stage(0, 0);
    fill_stage(1, 1);

    for (int it = 0; it < ITERS; it++) {
        const int s = it % 3;
        if (it < ITERS - 1) CP_WAIT1(); else CP_WAIT0();
        __syncthreads();                 // fill(it) visible; stage (it+2)%3 free
        if (it + 2 < ITERS) fill_stage((it + 2) % 3, it + 2);

        const uint32_t uA = tb + s * STAGE;
        const uint32_t uB = uA + 16384;
#pragma unroll
        for (int ks = 0; ks < 2; ks++) {
            const uint32_t kb = ks * 32;          // hi at +kb, lo at +64+kb
            uint32_t a[4][4], bh[4][2], bl[4][2];
            // B-hi: 2 x4 (each loads two n-frags)
#pragma unroll
            for (int p = 0; p < 2; p++)
                LDM_X4(bh[2 * p][0], bh[2 * p][1], bh[2 * p + 1][0], bh[2 * p + 1][1],
                       uB + ((bOff[p] + kb) ^ bXor[p]));
            // A-hi: 4 x4
#pragma unroll
            for (int tm = 0; tm < 4; tm++)
                LDM_X4(a[tm][0], a[tm][1], a[tm][2], a[tm][3],
                       uA + ((aOff[tm] + kb) ^ aXor[tm]));
            // B-lo prefetch (hidden under pass-1 MMAs)
#pragma unroll
            for (int p = 0; p < 2; p++)
                LDM_X4(bl[2 * p][0], bl[2 * p][1], bl[2 * p + 1][0], bl[2 * p + 1][1],
                       uB + ((bOff[p] + 64u + kb) ^ bXor[p]));
            // pass 1: Ah * Bh
#pragma unroll
            for (int tm = 0; tm < 4; tm++)
#pragma unroll
                for (int tn = 0; tn < 4; tn++)
                    MMA16816(acc[tm][tn], a[tm], bh[tn]);
            // pass 2: Ah * Bl
#pragma unroll
            for (int tm = 0; tm < 4; tm++)
#pragma unroll
                for (int tn = 0; tn < 4; tn++)
                    MMA16816(acc[tm][tn], a[tm], bl[tn]);
            // A-lo, then pass 3: Al * Bh
#pragma unroll
            for (int tm = 0; tm < 4; tm++)
                LDM_X4(a[tm][0], a[tm][1], a[tm][2], a[tm][3],
                       uA + ((aOff[tm] + 64u + kb) ^ aXor[tm]));
#pragma unroll
            for (int tm = 0; tm < 4; tm++)
#pragma unroll
                for (int tn = 0; tn < 4; tn++)
                    MMA16816(acc[tm][tn], a[tm], bh[tn]);
        }
    }

    // ---- epilogue: out = s_eff[b,oc]*y + bias[oc] (verified mapping) ----
    const int gID = lane >> 2;
    const int t4  = lane & 3;
    const float* scRow = g_scale + (b << 9) + ocBase;
#pragma unroll
    for (int tn = 0; tn < 4; tn++) {
        const int col0 = wn0 + tn * 8 + t4 * 2;
        const float sc0 = scRow[col0],  sc1 = scRow[col0 + 1];
        const float bs0 = conv_bias[ocBase + col0];
        const float bs1 = conv_bias[ocBase + col0 + 1];
        float* o0 = out + (((size_t)(b * COUT + ocBase + col0)) * 32 + h0) * 32;
        float* o1 = out + (((size_t)(b * COUT + ocBase + col0 + 1)) * 32 + h0) * 32;
#pragma unroll
        for (int tm = 0; tm < 4; tm++) {
            const int mA = wm0 + tm * 16 + gID;
            const int rA = mA >> 5, wA = mA & 31;
            const int mB = mA + 8;
            const int rB = mB >> 5, wB = mB & 31;
            o0[rA * 32 + wA] = acc[tm][tn][0] * sc0 + bs0;
            o1[rA * 32 + wA] = acc[tm][tn][1] * sc1 + bs1;
            o0[rB * 32 + wB] = acc[tm][tn][2] * sc0 + bs0;
            o1[rB * 32 + wB] = acc[tm][tn][3] * sc1 + bs1;
        }
    }
}

// ---------------------------------------------------------------------------
// Launch (4 kernels; conv last so ncu capture lands on it).
// Inputs: 0 x, 1 style_w, 2 conv_weight, 3 lin_w, 4 lin_b, 5 mod_bias,
//         6 conv_bias
// ---------------------------------------------------------------------------
extern "C" void kernel_launch(void* const* d_in, const int* in_sizes, int n_in,
                              void* d_out, int out_size) {
    const float* x         = (const float*)d_in[0];
    const float* style_w   = (const float*)d_in[1];
    const float* conv_w    = (const float*)d_in[2];
    const float* lin_w     = (const float*)d_in[3];
    const float* lin_b     = (const float*)d_in[4];
    const float* mod_bias  = (const float*)d_in[5];
    const float* conv_bias = (const float*)d_in[6];
    float* out = (float*)d_out;

    cudaFuncSetAttribute(conv_mma_kernel,
                         cudaFuncAttributeMaxDynamicSharedMemorySize, SMEM_SZ);

    trans_x_kernel<<<dim3(16, 544), dim3(32, 8)>>>(x);
    split_w_kernel<<<(NW + 255) / 256, 256>>>(conv_w);
    scale_kernel<<<COUT, 256>>>(conv_w, style_w, lin_w, lin_b, mod_bias);
    conv_mma_kernel<<<dim3(4, 128), 256, SMEM_SZ>>>(conv_bias, out);
}

// round 14
// speedup vs baseline: 1.0266x; 1.0266x over previous
#include <cuda_runtime.h>
#include <cuda_bf16.h>
#include <stdint.h>
#include <math.h>

// ---------------------------------------------------------------------------
// B=16, C_IN=512, C_OUT=512, K=3, LAT=256, H=W=32.
// Modulated conv == plain conv (raw weights) + per-(b,oc) scale + bias.
// Implicit GEMM on mma.sync bf16 (3-pass hi/lo split: xh*wh+xh*wl+xl*wh).
// Round-14: register-pressure relief — inline (non-hoisted) fill addressing,
// bl loaded after pass-1 (short live range), x4 B-fused ldmatrix kept.
// ---------------------------------------------------------------------------
#define BATCH   16
#define CIN     512
#define COUT    512
#define LAT     256
#define KR      4608
#define XP      34
#define XPP     (XP * XP)
#define NXT     (BATCH * XPP * CIN)
#define NW      (COUT * CIN)

#define EQ_LIN_F 0.08838834764831845f

// ---- device scratch (allocation-free) ----
__device__ __nv_bfloat16 g_xth[NXT];     // [b][hp][wp][ic] hi
__device__ __nv_bfloat16 g_xtl[NXT];     // [b][hp][wp][ic] lo
__device__ __nv_bfloat16 g_wh[9 * NW];   // [tap][oc][ic]
__device__ __nv_bfloat16 g_wl[9 * NW];
__device__ float         g_scale[BATCH * COUT];

// ---------------------------------------------------------------------------
// helpers
// ---------------------------------------------------------------------------
__device__ __forceinline__ uint32_t smem_u32(const void* p) {
    uint32_t a;
    asm("{ .reg .u64 t; cvta.to.shared.u64 t, %1; cvt.u32.u64 %0, t; }"
        : "=r"(a) : "l"(p));
    return a;
}
#define SW128(o) ((o) ^ ((((unsigned)(o)) >> 3) & 0x70u))

#define LDM_X4(r0, r1, r2, r3, a) \
    asm volatile("ldmatrix.sync.aligned.m8n8.x4.shared.b16 {%0,%1,%2,%3}, [%4];" \
        : "=r"(r0), "=r"(r1), "=r"(r2), "=r"(r3) : "r"(a))

#define MMA16816(d, a, b) \
    asm volatile("mma.sync.aligned.m16n8k16.row.col.f32.bf16.bf16.f32 " \
        "{%0,%1,%2,%3}, {%4,%5,%6,%7}, {%8,%9}, {%0,%1,%2,%3};" \
        : "+f"((d)[0]), "+f"((d)[1]), "+f"((d)[2]), "+f"((d)[3]) \
        : "r"((a)[0]), "r"((a)[1]), "r"((a)[2]), "r"((a)[3]), \
          "r"((b)[0]), "r"((b)[1]))

#define CP16(dst, src) \
    asm volatile("cp.async.cg.shared.global [%0], [%1], 16;" :: "r"(dst), "l"(src))
#define CP_COMMIT()  asm volatile("cp.async.commit_group;")
#define CP_WAIT0()   asm volatile("cp.async.wait_group 0;" ::: "memory")
#define CP_WAIT1()   asm volatile("cp.async.wait_group 1;" ::: "memory")

// ---------------------------------------------------------------------------
// 1) transpose + split x -> xT[b][h+1][w+1][ic] hi/lo; by>=512 blocks write
//    the zero borders (hp or wp in {0,33}); disjoint from interior writes.
// ---------------------------------------------------------------------------
__global__ void trans_x_kernel(const float* __restrict__ x) {
    __shared__ float tile[32][33];
    const int tx = threadIdx.x, ty = threadIdx.y;
    const int tid = ty * 32 + tx;
    if (blockIdx.y >= 512) {
        const int base = ((int)blockIdx.y - 512) * 256 + tid;   // 0..8191
        for (int e = 0; e < 132; e++) {
            const int g = base + e * 8192;
            const int ic = g & 511;
            const int r  = g >> 9;
            const int p  = r % 132;
            const int b  = r / 132;
            int hp, wp;
            if      (p < 34)  { hp = 0;       wp = p; }
            else if (p < 68)  { hp = 33;      wp = p - 34; }
            else if (p < 100) { hp = p - 67;  wp = 0; }
            else              { hp = p - 99;  wp = 33; }
            const size_t idx = ((size_t)(b * XP + hp) * XP + wp) * CIN + ic;
            g_xth[idx] = __float2bfloat16(0.f);
            g_xtl[idx] = __float2bfloat16(0.f);
        }
        return;
    }
    const int ic0 = blockIdx.x * 32;
    const int b   = blockIdx.y >> 5;
    const int h   = blockIdx.y & 31;
#pragma unroll
    for (int i = 0; i < 4; i++) {
        const int icl = ty + 8 * i;
        tile[icl][tx] = x[(((size_t)b * CIN + ic0 + icl) * 32 + h) * 32 + tx];
    }
    __syncthreads();
#pragma unroll
    for (int jj = 0; jj < 4; jj++) {
        const int j = ty + 8 * jj;
        const float v = tile[tx][j];
        const __nv_bfloat16 hi = __float2bfloat16(v);
        const size_t idx = ((size_t)(b * XP + h + 1) * XP + (j + 1)) * CIN + ic0 + tx;
        g_xth[idx] = hi;
        g_xtl[idx] = __float2bfloat16(v - __bfloat162float(hi));
    }
}

// ---------------------------------------------------------------------------
// 2) split + per-tap transpose weights -> g_wh/g_wl [tap][oc][ic]
// ---------------------------------------------------------------------------
__global__ void split_w_kernel(const float* __restrict__ w) {
    int i = blockIdx.x * blockDim.x + threadIdx.x;   // oc*512 + ic
    if (i >= NW) return;
    const float* src = w + (size_t)i * 9;
#pragma unroll
    for (int t = 0; t < 9; t++) {
        const float v = src[t];
        const __nv_bfloat16 h = __float2bfloat16(v);
        g_wh[(size_t)t * NW + i] = h;
        g_wl[(size_t)t * NW + i] = __float2bfloat16(v - __bfloat162float(h));
    }
}

// ---------------------------------------------------------------------------
// 3) per-(b,oc) effective scale; vectorized reduction
// ---------------------------------------------------------------------------
__global__ void scale_kernel(const float* __restrict__ W,
                             const float* __restrict__ style_w,
                             const float* __restrict__ lin_w,
                             const float* __restrict__ lin_b,
                             const float* __restrict__ mod_bias) {
    const int o = blockIdx.x;
    __shared__ float red[256];
    float ss = 0.f;
    const float4* wrow = (const float4*)(W + (size_t)o * KR);
    for (int i = threadIdx.x; i < KR / 4; i += 256) {
        const float4 v = wrow[i];
        ss += v.x * v.x + v.y * v.y + v.z * v.z + v.w * v.w;
    }
    red[threadIdx.x] = ss;
    __syncthreads();
#pragma unroll
    for (int s = 128; s > 0; s >>= 1) {
        if (threadIdx.x < s) red[threadIdx.x] += red[threadIdx.x + s];
        __syncthreads();
    }
    const float sumsq = red[0];
    if (threadIdx.x < BATCH) {
        const int b = threadIdx.x;
        const float4* st = (const float4*)(style_w + b * LAT);
        const float4* lw = (const float4*)(lin_w + (size_t)o * LAT);
        float dot = 0.f;
#pragma unroll 8
        for (int l = 0; l < LAT / 4; l++) {
            const float4 a = st[l], c = lw[l];
            dot += a.x * c.x + a.y * c.y + a.z * c.z + a.w * c.w;
        }
        const float eq_conv = sqrtf(2.0f / (float)KR);
        const float s = dot * EQ_LIN_F + lin_b[o] + 1.0f + mod_bias[o];
        g_scale[b * COUT + o] =
            eq_conv * s * rsqrtf(s * s * eq_conv * eq_conv * sumsq + 1e-8f);
    }
}

// ---------------------------------------------------------------------------
// 4) main mma.sync kernel, 3-stage pipeline, low register pressure.
//    CTA: M=128 x N=128; grid (4,128); 8 warps 2x4 -> 64x32 warp tiles.
//    144 iters (9 taps x 16 ic-chunks of 32). Stage 32KB: A[128m][32ic hi|lo],
//    B[128oc][same], SW128 rows. Fill addresses recomputed inline per call.
// ---------------------------------------------------------------------------
#define ITERS   144
#define STAGE   32768
#define SMEM_SZ (3 * STAGE + 1024)

__global__ __launch_bounds__(256, 2)
void conv_mma_kernel(const float* __restrict__ conv_bias, float* __restrict__ out) {
    extern __shared__ __align__(1024) char dsm[];
    const uint32_t sb = smem_u32(dsm);
    const uint32_t tb = (sb + 1023u) & ~1023u;

    const int t    = threadIdx.x;
    const int wid  = t >> 5, lane = t & 31;
    const int ocBase = blockIdx.x * 128;
    const int mT = blockIdx.y;
    const int b  = mT >> 3;
    const int h0 = (mT & 7) * 4;

    const int wm0 = (wid & 1) * 64;
    const int wn0 = (wid >> 1) * 32;

    // fragment offsets (stage-relative) + row-XOR; addr = base+((off+kb)^xor)
    uint32_t aOff[4], aXor[4], bOff[2], bXor[2];
    {
        const int rA = lane & 15;
        const int ha = lane >> 4;
#pragma unroll
        for (int tm = 0; tm < 4; tm++) {
            const uint32_t off = (uint32_t)(wm0 + tm * 16 + rA) * 128u + ha * 16u;
            aOff[tm] = off;
            aXor[tm] = (off >> 3) & 0x70u;
        }
        // B x4 (two n-frags per load): lanes 0-7 frag 2p k-lo, 8-15 frag 2p
        // k-hi, 16-23 frag 2p+1 k-lo, 24-31 frag 2p+1 k-hi
        const int rB = (lane & 7) + ((lane >> 4) & 1) * 8;
        const int hb = (lane >> 3) & 1;
#pragma unroll
        for (int p = 0; p < 2; p++) {
            const uint32_t off = (uint32_t)(wn0 + p * 16 + rB) * 128u + hb * 16u;
            bOff[p] = off;
            bXor[p] = (off >> 3) & 0x70u;
        }
    }

    float acc[4][4][4];
#pragma unroll
    for (int i = 0; i < 4; i++)
#pragma unroll
        for (int j = 0; j < 4; j++)
#pragma unroll
            for (int k = 0; k < 4; k++) acc[i][j][k] = 0.f;

    // fill: addresses computed inline (transient registers only)
    auto fill_stage = [&](int s, int it) {
        const int tap = it >> 4;
        const int ic0 = (it & 15) << 5;
        const int dh = tap / 3, dw = tap - dh * 3;
        const int q   = t & 7;
        const int v   = q >> 2;
        const int sub = q & 3;
        const int r5  = t >> 3;                   // 0..31
        const __nv_bfloat16* aPtr = (v ? g_xtl : g_xth)
            + ((size_t)((b * XP + h0 + dh) * XP + dw + r5) << 9) + ic0 + (sub << 3);
        const __nv_bfloat16* bPtr = (v ? g_wl : g_wh)
            + (size_t)tap * NW + ((size_t)(ocBase + r5) << 9) + ic0 + (sub << 3);
        const uint32_t uA = tb + s * STAGE;
        const uint32_t uB = uA + 16384;
#pragma unroll
        for (int kk = 0; kk < 4; kk++) {
            const uint32_t doff =
                SW128((uint32_t)((kk * 32 + r5) << 7) + (v << 6) + (sub << 4));
            CP16(uA + doff, aPtr + ((size_t)(kk * XP) << 9));
            CP16(uB + doff, bPtr + ((size_t)(kk * 32) << 9));
        }
        CP_COMMIT();
    };

    fill_stage(0, 0);
    fill_stage(1, 1);

    for (int it = 0; it < ITERS; it++) {
        const int s = it % 3;
        if (it < ITERS - 1) CP_WAIT1(); else CP_WAIT0();
        __syncthreads();                 // fill(it) visible; stage (it+2)%3 free
        if (it + 2 < ITERS) fill_stage((it + 2) % 3, it + 2);

        const uint32_t uA = tb + s * STAGE;
        const uint32_t uB = uA + 16384;
#pragma unroll
        for (int ks = 0; ks < 2; ks++) {
            const uint32_t kb = ks * 32;          // hi at +kb, lo at +64+kb
            uint32_t a[4][4], bh[4][2], bl[4][2];
            // B-hi: 2 x4 (each loads two n-frags)
#pragma unroll
            for (int p = 0; p < 2; p++)
                LDM_X4(bh[2 * p][0], bh[2 * p][1], bh[2 * p + 1][0], bh[2 * p + 1][1],
                       uB + ((bOff[p] + kb) ^ bXor[p]));
            // A-hi: 4 x4
#pragma unroll
            for (int tm = 0; tm < 4; tm++)
                LDM_X4(a[tm][0], a[tm][1], a[tm][2], a[tm][3],
                       uA + ((aOff[tm] + kb) ^ aXor[tm]));
            // pass 1: Ah * Bh
#pragma unroll
            for (int tm = 0; tm < 4; tm++)
#pragma unroll
                for (int tn = 0; tn < 4; tn++)
                    MMA16816(acc[tm][tn], a[tm], bh[tn]);
            // B-lo (short live range: pass 2 only)
#pragma unroll
            for (int p = 0; p < 2; p++)
                LDM_X4(bl[2 * p][0], bl[2 * p][1], bl[2 * p + 1][0], bl[2 * p + 1][1],
                       uB + ((bOff[p] + 64u + kb) ^ bXor[p]));
            // pass 2: Ah * Bl
#pragma unroll
            for (int tm = 0; tm < 4; tm++)
#pragma unroll
                for (int tn = 0; tn < 4; tn++)
                    MMA16816(acc[tm][tn], a[tm], bl[tn]);
            // A-lo (overwrites a), pass 3: Al * Bh
#pragma unroll
            for (int tm = 0; tm < 4; tm++)
                LDM_X4(a[tm][0], a[tm][1], a[tm][2], a[tm][3],
                       uA + ((aOff[tm] + 64u + kb) ^ aXor[tm]));
#pragma unroll
            for (int tm = 0; tm < 4; tm++)
#pragma unroll
                for (int tn = 0; tn < 4; tn++)
                    MMA16816(acc[tm][tn], a[tm], bh[tn]);
        }
    }

    // ---- epilogue: out = s_eff[b,oc]*y + bias[oc] (verified mapping) ----
    const int gID = lane >> 2;
    const int t4  = lane & 3;
    const float* scRow = g_scale + (b << 9) + ocBase;
#pragma unroll
    for (int tn = 0; tn < 4; tn++) {
        const int col0 = wn0 + tn * 8 + t4 * 2;
        const float sc0 = scRow[col0],  sc1 = scRow[col0 + 1];
        const float bs0 = conv_bias[ocBase + col0];
        const float bs1 = conv_bias[ocBase + col0 + 1];
        float* o0 = out + (((size_t)(b * COUT + ocBase + col0)) * 32 + h0) * 32;
        float* o1 = out + (((size_t)(b * COUT + ocBase + col0 + 1)) * 32 + h0) * 32;
#pragma unroll
        for (int tm = 0; tm < 4; tm++) {
            const int mA = wm0 + tm * 16 + gID;
            const int rA = mA >> 5, wA = mA & 31;
            const int mB = mA + 8;
            const int rB = mB >> 5, wB = mB & 31;
            o0[rA * 32 + wA] = acc[tm][tn][0] * sc0 + bs0;
            o1[rA * 32 + wA] = acc[tm][tn][1] * sc1 + bs1;
            o0[rB * 32 + wB] = acc[tm][tn][2] * sc0 + bs0;
            o1[rB * 32 + wB] = acc[tm][tn][3] * sc1 + bs1;
        }
    }
}

// ---------------------------------------------------------------------------
// Launch (4 kernels; conv last so ncu capture lands on it).
// Inputs: 0 x, 1 style_w, 2 conv_weight, 3 lin_w, 4 lin_b, 5 mod_bias,
//         6 conv_bias
// ---------------------------------------------------------------------------
extern "C" void kernel_launch(void* const* d_in, const int* in_sizes, int n_in,
                              void* d_out, int out_size) {
    const float* x         = (const float*)d_in[0];
    const float* style_w   = (const float*)d_in[1];
    const float* conv_w    = (const float*)d_in[2];
    const float* lin_w     = (const float*)d_in[3];
    const float* lin_b     = (const float*)d_in[4];
    const float* mod_bias  = (const float*)d_in[5];
    const float* conv_bias = (const float*)d_in[6];
    float* out = (float*)d_out;

    cudaFuncSetAttribute(conv_mma_kernel,
                         cudaFuncAttributeMaxDynamicSharedMemorySize, SMEM_SZ);

    trans_x_kernel<<<dim3(16, 544), dim3(32, 8)>>>(x);
    split_w_kernel<<<(NW + 255) / 256, 256>>>(conv_w);
    scale_kernel<<<COUT, 256>>>(conv_w, style_w, lin_w, lin_b, mod_bias);
    conv_mma_kernel<<<dim3(4, 128), 256, SMEM_SZ>>>(conv_bias, out);
}

// round 15
// speedup vs baseline: 1.0724x; 1.0446x over previous
#include <cuda_runtime.h>
#include <cuda_bf16.h>
#include <stdint.h>
#include <math.h>

// ---------------------------------------------------------------------------
// B=16, C_IN=512, C_OUT=512, K=3, LAT=256, H=W=32.
// Modulated conv == plain conv (raw weights) + per-(b,oc) scale + bias.
// Implicit GEMM on mma.sync bf16 (3-pass hi/lo split: xh*wh+xh*wl+xl*wh).
// Round-15: cp.async issue-rate relief. Chunk-major loop (16 ic-chunks x 9
// taps); per chunk ONE A halo tile [6x34 pos][32ic hi|lo] (26KB) serves all
// 9 taps; per tap only B (16KB). cp.async ops/iter: 2048 -> ~1200.
// ---------------------------------------------------------------------------
#define BATCH   16
#define CIN     512
#define COUT    512
#define LAT     256
#define KR      4608
#define XP      34
#define XPP     (XP * XP)
#define NXT     (BATCH * XPP * CIN)
#define NW      (COUT * CIN)

#define EQ_LIN_F 0.08838834764831845f

// ---- device scratch (allocation-free) ----
__device__ __nv_bfloat16 g_xth[NXT];     // [b][hp][wp][ic] hi
__device__ __nv_bfloat16 g_xtl[NXT];     // [b][hp][wp][ic] lo
__device__ __nv_bfloat16 g_wh[9 * NW];   // [tap][oc][ic]
__device__ __nv_bfloat16 g_wl[9 * NW];
__device__ float         g_scale[BATCH * COUT];

// ---------------------------------------------------------------------------
// helpers
// ---------------------------------------------------------------------------
__device__ __forceinline__ uint32_t smem_u32(const void* p) {
    uint32_t a;
    asm("{ .reg .u64 t; cvta.to.shared.u64 t, %1; cvt.u32.u64 %0, t; }"
        : "=r"(a) : "l"(p));
    return a;
}
#define SW128(o) ((o) ^ ((((unsigned)(o)) >> 3) & 0x70u))

#define LDM_X4(r0, r1, r2, r3, a) \
    asm volatile("ldmatrix.sync.aligned.m8n8.x4.shared.b16 {%0,%1,%2,%3}, [%4];" \
        : "=r"(r0), "=r"(r1), "=r"(r2), "=r"(r3) : "r"(a))

#define MMA16816(d, a, b) \
    asm volatile("mma.sync.aligned.m16n8k16.row.col.f32.bf16.bf16.f32 " \
        "{%0,%1,%2,%3}, {%4,%5,%6,%7}, {%8,%9}, {%0,%1,%2,%3};" \
        : "+f"((d)[0]), "+f"((d)[1]), "+f"((d)[2]), "+f"((d)[3]) \
        : "r"((a)[0]), "r"((a)[1]), "r"((a)[2]), "r"((a)[3]), \
          "r"((b)[0]), "r"((b)[1]))

#define CP16(dst, src) \
    asm volatile("cp.async.cg.shared.global [%0], [%1], 16;" :: "r"(dst), "l"(src))
#define CP_COMMIT()  asm volatile("cp.async.commit_group;")
#define CP_WAIT0()   asm volatile("cp.async.wait_group 0;" ::: "memory")
#define CP_WAIT1()   asm volatile("cp.async.wait_group 1;" ::: "memory")

// ---------------------------------------------------------------------------
// 1) transpose + split x -> xT[b][h+1][w+1][ic] hi/lo; by>=512 blocks write
//    the zero borders (hp or wp in {0,33}).
// ---------------------------------------------------------------------------
__global__ void trans_x_kernel(const float* __restrict__ x) {
    __shared__ float tile[32][33];
    const int tx = threadIdx.x, ty = threadIdx.y;
    const int tid = ty * 32 + tx;
    if (blockIdx.y >= 512) {
        const int base = ((int)blockIdx.y - 512) * 256 + tid;   // 0..8191
        for (int e = 0; e < 132; e++) {
            const int g = base + e * 8192;
            const int ic = g & 511;
            const int r  = g >> 9;
            const int p  = r % 132;
            const int b  = r / 132;
            int hp, wp;
            if      (p < 34)  { hp = 0;       wp = p; }
            else if (p < 68)  { hp = 33;      wp = p - 34; }
            else if (p < 100) { hp = p - 67;  wp = 0; }
            else              { hp = p - 99;  wp = 33; }
            const size_t idx = ((size_t)(b * XP + hp) * XP + wp) * CIN + ic;
            g_xth[idx] = __float2bfloat16(0.f);
            g_xtl[idx] = __float2bfloat16(0.f);
        }
        return;
    }
    const int ic0 = blockIdx.x * 32;
    const int b   = blockIdx.y >> 5;
    const int h   = blockIdx.y & 31;
#pragma unroll
    for (int i = 0; i < 4; i++) {
        const int icl = ty + 8 * i;
        tile[icl][tx] = x[(((size_t)b * CIN + ic0 + icl) * 32 + h) * 32 + tx];
    }
    __syncthreads();
#pragma unroll
    for (int jj = 0; jj < 4; jj++) {
        const int j = ty + 8 * jj;
        const float v = tile[tx][j];
        const __nv_bfloat16 hi = __float2bfloat16(v);
        const size_t idx = ((size_t)(b * XP + h + 1) * XP + (j + 1)) * CIN + ic0 + tx;
        g_xth[idx] = hi;
        g_xtl[idx] = __float2bfloat16(v - __bfloat162float(hi));
    }
}

// ---------------------------------------------------------------------------
// 2) split + per-tap transpose weights -> g_wh/g_wl [tap][oc][ic]
// ---------------------------------------------------------------------------
__global__ void split_w_kernel(const float* __restrict__ w) {
    int i = blockIdx.x * blockDim.x + threadIdx.x;   // oc*512 + ic
    if (i >= NW) return;
    const float* src = w + (size_t)i * 9;
#pragma unroll
    for (int t = 0; t < 9; t++) {
        const float v = src[t];
        const __nv_bfloat16 h = __float2bfloat16(v);
        g_wh[(size_t)t * NW + i] = h;
        g_wl[(size_t)t * NW + i] = __float2bfloat16(v - __bfloat162float(h));
    }
}

// ---------------------------------------------------------------------------
// 3) per-(b,oc) effective scale; vectorized reduction
// ---------------------------------------------------------------------------
__global__ void scale_kernel(const float* __restrict__ W,
                             const float* __restrict__ style_w,
                             const float* __restrict__ lin_w,
                             const float* __restrict__ lin_b,
                             const float* __restrict__ mod_bias) {
    const int o = blockIdx.x;
    __shared__ float red[256];
    float ss = 0.f;
    const float4* wrow = (const float4*)(W + (size_t)o * KR);
    for (int i = threadIdx.x; i < KR / 4; i += 256) {
        const float4 v = wrow[i];
        ss += v.x * v.x + v.y * v.y + v.z * v.z + v.w * v.w;
    }
    red[threadIdx.x] = ss;
    __syncthreads();
#pragma unroll
    for (int s = 128; s > 0; s >>= 1) {
        if (threadIdx.x < s) red[threadIdx.x] += red[threadIdx.x + s];
        __syncthreads();
    }
    const float sumsq = red[0];
    if (threadIdx.x < BATCH) {
        const int b = threadIdx.x;
        const float4* st = (const float4*)(style_w + b * LAT);
        const float4* lw = (const float4*)(lin_w + (size_t)o * LAT);
        float dot = 0.f;
#pragma unroll 8
        for (int l = 0; l < LAT / 4; l++) {
            const float4 a = st[l], c = lw[l];
            dot += a.x * c.x + a.y * c.y + a.z * c.z + a.w * c.w;
        }
        const float eq_conv = sqrtf(2.0f / (float)KR);
        const float s = dot * EQ_LIN_F + lin_b[o] + 1.0f + mod_bias[o];
        g_scale[b * COUT + o] =
            eq_conv * s * rsqrtf(s * s * eq_conv * eq_conv * sumsq + 1e-8f);
    }
}

// ---------------------------------------------------------------------------
// 4) main mma.sync kernel, chunk-major halo-A pipeline.
//    CTA: M=128 x N=128; grid (4,128); 8 warps 2x4 -> 64x32 warp tiles.
//    it = ch*9 + tap, 144 iters. A: 2 stages x 26KB ([204 pos][32ic hi|lo]),
//    filled once per chunk (rides tap-0 commit). B: 3 stages x 16KB, per tap.
// ---------------------------------------------------------------------------
#define ITERS   144
#define ASTAGE  26624               // 204*128 = 26112, padded to 26*1024
#define BSTAGE  16384
#define B_BASE  (2 * ASTAGE)        // 53248
#define SMEM_SZ (B_BASE + 3 * BSTAGE + 1024)

__global__ __launch_bounds__(256, 2)
void conv_mma_kernel(const float* __restrict__ conv_bias, float* __restrict__ out) {
    extern __shared__ __align__(1024) char dsm[];
    const uint32_t sb = smem_u32(dsm);
    const uint32_t tb = (sb + 1023u) & ~1023u;

    const int t    = threadIdx.x;
    const int wid  = t >> 5, lane = t & 31;
    const int ocBase = blockIdx.x * 128;
    const int mT = blockIdx.y;
    const int b  = mT >> 3;
    const int h0 = (mT & 7) * 4;

    const int wm0 = (wid & 1) * 64;
    const int wn0 = (wid >> 1) * 32;

    // A fragment lane constants: m = wm0 + tm*16 + (lane&15) -> (rm, cm)
    const int ha = lane >> 4;                 // k half (0/1 -> +8)
    int rm[4], cm[4];
#pragma unroll
    for (int tm = 0; tm < 4; tm++) {
        const int m = wm0 + tm * 16 + (lane & 15);
        rm[tm] = m >> 5;                      // output row 0..3
        cm[tm] = m & 31;                      // output col
    }

    // B fragment offsets (x4 = two n-frags per load)
    uint32_t bOff[2], bXor[2];
    {
        const int rB = (lane & 7) + ((lane >> 4) & 1) * 8;
        const int hb = (lane >> 3) & 1;
#pragma unroll
        for (int p = 0; p < 2; p++) {
            const uint32_t off = (uint32_t)(wn0 + p * 16 + rB) * 128u + hb * 16u;
            bOff[p] = off;
            bXor[p] = (off >> 3) & 0x70u;
        }
    }

    float acc[4][4][4];
#pragma unroll
    for (int i = 0; i < 4; i++)
#pragma unroll
        for (int j = 0; j < 4; j++)
#pragma unroll
            for (int k = 0; k < 4; k++) acc[i][j][k] = 0.f;

    // per-thread fill constants
    const int q   = t & 7;
    const int v   = q >> 2;
    const int sub = q & 3;
    const int r5  = t >> 3;                   // 0..31

    // B fill: 1024 CP16 (4 per thread), verified layout
    auto fill_B = [&](int s, int it) {
        const int ch  = it / 9;
        const int tap = it - 9 * ch;
        const int ic0 = ch << 5;
        const __nv_bfloat16* bPtr = (v ? g_wl : g_wh)
            + (size_t)tap * NW + ((size_t)(ocBase + r5) << 9) + ic0 + (sub << 3);
        const uint32_t uB = tb + B_BASE + s * BSTAGE;
#pragma unroll
        for (int kk = 0; kk < 4; kk++) {
            const uint32_t doff =
                SW128((uint32_t)((kk * 32 + r5) << 7) + (v << 6) + (sub << 4));
            CP16(uB + doff, bPtr + ((size_t)(kk * 32) << 9));
        }
    };

    // A halo fill: [204 pos = rr*34+cc][32ic hi|lo], 1632 CP16 per chunk
    auto fill_A = [&](int sa, int ch) {
        const int ic0 = ch << 5;
        const __nv_bfloat16* base = (v ? g_xtl : g_xth);
        const uint32_t uA = tb + sa * ASTAGE;
#pragma unroll
        for (int k = 0; k < 7; k++) {
            const int p = r5 + 32 * k;
            if (p < 204) {
                const int rr = p / 34;
                const int cc = p - 34 * rr;
                const uint32_t doff =
                    SW128((uint32_t)(p << 7) + (v << 6) + (sub << 4));
                CP16(uA + doff,
                     base + ((size_t)((b * XP + h0 + rr) * XP + cc) << 9)
                          + ic0 + (sub << 3));
            }
        }
    };

    // prologue: group0 = A(0)+B(0), group1 = B(1)
    fill_A(0, 0); fill_B(0, 0); CP_COMMIT();
    fill_B(1, 1); CP_COMMIT();

    for (int it = 0; it < ITERS; it++) {
        const int ch  = it / 9;
        const int tap = it - 9 * ch;
        const int dh = tap / 3, dw = tap - dh * 3;

        if (it < ITERS - 1) CP_WAIT1(); else CP_WAIT0();
        __syncthreads();             // fills for it visible; old stages free

        // next fills (exactly one commit per iter keeps wait_group counting)
        if (it + 2 < ITERS) fill_B((it + 2) % 3, it + 2);
        if (tap == 0 && ch + 1 < 16) fill_A((ch + 1) & 1, ch + 1);
        CP_COMMIT();

        const uint32_t uA = tb + (ch & 1) * ASTAGE;
        const uint32_t uB = tb + B_BASE + (it % 3) * BSTAGE;

        // per-tap A fragment offsets: lane row = (rm+dh)*34 + cm+dw
        uint32_t aOff[4], aXor[4];
#pragma unroll
        for (int tm = 0; tm < 4; tm++) {
            const uint32_t off =
                (uint32_t)((rm[tm] + dh) * 34 + cm[tm] + dw) * 128u + ha * 16u;
            aOff[tm] = off;
            aXor[tm] = (off >> 3) & 0x70u;
        }

#pragma unroll
        for (int ks = 0; ks < 2; ks++) {
            const uint32_t kb = ks * 32;          // hi at +kb, lo at +64+kb
            uint32_t a[4][4], bh[4][2], bl[4][2];
#pragma unroll
            for (int p = 0; p < 2; p++)
                LDM_X4(bh[2 * p][0], bh[2 * p][1], bh[2 * p + 1][0], bh[2 * p + 1][1],
                       uB + ((bOff[p] + kb) ^ bXor[p]));
#pragma unroll
            for (int tm = 0; tm < 4; tm++)
                LDM_X4(a[tm][0], a[tm][1], a[tm][2], a[tm][3],
                       uA + ((aOff[tm] + kb) ^ aXor[tm]));
            // pass 1: Ah * Bh
#pragma unroll
            for (int tm = 0; tm < 4; tm++)
#pragma unroll
                for (int tn = 0; tn < 4; tn++)
                    MMA16816(acc[tm][tn], a[tm], bh[tn]);
            // B-lo
#pragma unroll
            for (int p = 0; p < 2; p++)
                LDM_X4(bl[2 * p][0], bl[2 * p][1], bl[2 * p + 1][0], bl[2 * p + 1][1],
                       uB + ((bOff[p] + 64u + kb) ^ bXor[p]));
            // pass 2: Ah * Bl
#pragma unroll
            for (int tm = 0; tm < 4; tm++)
#pragma unroll
                for (int tn = 0; tn < 4; tn++)
                    MMA16816(acc[tm][tn], a[tm], bl[tn]);
            // A-lo, pass 3: Al * Bh
#pragma unroll
            for (int tm = 0; tm < 4; tm++)
                LDM_X4(a[tm][0], a[tm][1], a[tm][2], a[tm][3],
                       uA + ((aOff[tm] + 64u + kb) ^ aXor[tm]));
#pragma unroll
            for (int tm = 0; tm < 4; tm++)
#pragma unroll
                for (int tn = 0; tn < 4; tn++)
                    MMA16816(acc[tm][tn], a[tm], bh[tn]);
        }
    }

    // ---- epilogue: out = s_eff[b,oc]*y + bias[oc] (verified mapping) ----
    const int gID = lane >> 2;
    const int t4  = lane & 3;
    const float* scRow = g_scale + (b << 9) + ocBase;
#pragma unroll
    for (int tn = 0; tn < 4; tn++) {
        const int col0 = wn0 + tn * 8 + t4 * 2;
        const float sc0 = scRow[col0],  sc1 = scRow[col0 + 1];
        const float bs0 = conv_bias[ocBase + col0];
        const float bs1 = conv_bias[ocBase + col0 + 1];
        float* o0 = out + (((size_t)(b * COUT + ocBase + col0)) * 32 + h0) * 32;
        float* o1 = out + (((size_t)(b * COUT + ocBase + col0 + 1)) * 32 + h0) * 32;
#pragma unroll
        for (int tm = 0; tm < 4; tm++) {
            const int mA = wm0 + tm * 16 + gID;
            const int rA = mA >> 5, wA = mA & 31;
            const int mB = mA + 8;
            const int rB = mB >> 5, wB = mB & 31;
            o0[rA * 32 + wA] = acc[tm][tn][0] * sc0 + bs0;
            o1[rA * 32 + wA] = acc[tm][tn][1] * sc1 + bs1;
            o0[rB * 32 + wB] = acc[tm][tn][2] * sc0 + bs0;
            o1[rB * 32 + wB] = acc[tm][tn][3] * sc1 + bs1;
        }
    }
}

// ---------------------------------------------------------------------------
// Launch (4 kernels; conv last so ncu capture lands on it).
// Inputs: 0 x, 1 style_w, 2 conv_weight, 3 lin_w, 4 lin_b, 5 mod_bias,
//         6 conv_bias
// ---------------------------------------------------------------------------
extern "C" void kernel_launch(void* const* d_in, const int* in_sizes, int n_in,
                              void* d_out, int out_size) {
    const float* x         = (const float*)d_in[0];
    const float* style_w   = (const float*)d_in[1];
    const float* conv_w    = (const float*)d_in[2];
    const float* lin_w     = (const float*)d_in[3];
    const float* lin_b     = (const float*)d_in[4];
    const float* mod_bias  = (const float*)d_in[5];
    const float* conv_bias = (const float*)d_in[6];
    float* out = (float*)d_out;

    cudaFuncSetAttribute(conv_mma_kernel,
                         cudaFuncAttributeMaxDynamicSharedMemorySize, SMEM_SZ);

    trans_x_kernel<<<dim3(16, 544), dim3(32, 8)>>>(x);
    split_w_kernel<<<(NW + 255) / 256, 256>>>(conv_w);
    scale_kernel<<<COUT, 256>>>(conv_w, style_w, lin_w, lin_b, mod_bias);
    conv_mma_kernel<<<dim3(4, 128), 256, SMEM_SZ>>>(conv_bias, out);
}